// round 4
// baseline (speedup 1.0000x reference)
#include <cuda_runtime.h>
#include <cstdint>
#include <cstddef>

// ---------------- problem constants ----------------
#define NNODES   100000
#define DFEAT    256
#define MAXDEG   128
#define BATCH    1024
#define FAN1     25
#define FAN2     10
#define OUTD     128           // per-branch output
#define M1       (BATCH*FAN1)          // 25600
#define M2       (BATCH*FAN1*FAN2)     // 256000

// ---------------- scratch (device globals; no allocation APIs) ----------------
__device__ int   d_cols1[FAN1];
__device__ int   d_cols2[FAN2];
__device__ int   d_ids1[M1];
__device__ int   d_ids2[M2];
__device__ float d_m2[M1 * DFEAT];     // mean over fan2 of feats[ids2]
__device__ float d_z1[M1 * DFEAT];     // layer-1 output for ids1 rows
__device__ float d_m1[BATCH * DFEAT];  // mean over fan1 of feats[ids1]
__device__ float d_z0[BATCH * DFEAT];  // layer-1 output for ids rows
__device__ float d_m3[BATCH * DFEAT];  // mean over fan1 of z1
__device__ float d_Wt[4 * DFEAT * OUTD]; // transposed weights [k][c]

// ---------------- threefry2x32 (JAX-exact, 20 rounds) ----------------
__device__ __forceinline__ uint32_t rotl32(uint32_t v, int r) {
    return (v << r) | (v >> (32 - r));
}

__device__ __forceinline__ void tf2x32(uint32_t k0, uint32_t k1,
                                       uint32_t x0, uint32_t x1,
                                       uint32_t& y0, uint32_t& y1) {
    uint32_t ks0 = k0, ks1 = k1, ks2 = k0 ^ k1 ^ 0x1BD11BDAu;
    x0 += ks0; x1 += ks1;
    const int r0[4] = {13, 15, 26, 6};
    const int r1[4] = {17, 29, 16, 24};
#define TF_G(RR) { x0 += x1; x1 = rotl32(x1, RR[0]); x1 ^= x0; \
                   x0 += x1; x1 = rotl32(x1, RR[1]); x1 ^= x0; \
                   x0 += x1; x1 = rotl32(x1, RR[2]); x1 ^= x0; \
                   x0 += x1; x1 = rotl32(x1, RR[3]); x1 ^= x0; }
    TF_G(r0); x0 += ks1; x1 += ks2 + 1u;
    TF_G(r1); x0 += ks2; x1 += ks0 + 2u;
    TF_G(r0); x0 += ks0; x1 += ks1 + 3u;
    TF_G(r1); x0 += ks1; x1 += ks2 + 4u;
    TF_G(r0); x0 += ks2; x1 += ks0 + 5u;
#undef TF_G
    y0 = x0; y1 = x1;
}

// Reproduce jax.random.permutation(k, 128) for k1,k2 = split(key(42)),
// with jax_threefry_partitionable=True semantics:
//   split(key)[i]  = full (y0,y1) of threefry(key, (0, i))   (foldlike split)
//   random_bits 32 = shift_right_logical(bits1, 32-32) ^ bits2 = y0 ^ y1
//                    of threefry(subkey, (0, i))
//   one shuffle round (ceil(3*ln128/ln(2^32-1)) = 1), stable ascending sort
//   of bits carries arange -> permutation
__global__ void setup_perm_kernel() {
    int t = threadIdx.x;  // 128 threads
    uint32_t k1a, k1b, k2a, k2b;
    tf2x32(0u, 42u, 0u, 0u, k1a, k1b);   // k1 = block (0,0)
    tf2x32(0u, 42u, 0u, 1u, k2a, k2b);   // k2 = block (0,1)
    uint32_t s1a, s1b, s2a, s2b;
    tf2x32(k1a, k1b, 0u, 1u, s1a, s1b);  // subkey of shuffle round for k1
    tf2x32(k2a, k2b, 0u, 1u, s2a, s2b);  // subkey for k2

    __shared__ uint32_t keys[MAXDEG];
    uint32_t b1, b2;

    // perm1: sort keys = y0 ^ y1 of threefry(subkey1, (0, t))
    tf2x32(s1a, s1b, 0u, (uint32_t)t, b1, b2);
    keys[t] = b1 ^ b2;
    __syncthreads();
    {
        uint32_t me = keys[t];
        int rank = 0;
        #pragma unroll 8
        for (int j = 0; j < MAXDEG; j++) {
            uint32_t kj = keys[j];
            rank += (kj < me) || (kj == me && j < t);
        }
        if (rank < FAN1) d_cols1[rank] = t;
    }
    __syncthreads();

    // perm2: sort keys = y0 ^ y1 of threefry(subkey2, (0, t))
    tf2x32(s2a, s2b, 0u, (uint32_t)t, b1, b2);
    keys[t] = b1 ^ b2;
    __syncthreads();
    {
        uint32_t me = keys[t];
        int rank = 0;
        #pragma unroll 8
        for (int j = 0; j < MAXDEG; j++) {
            uint32_t kj = keys[j];
            rank += (kj < me) || (kj == me && j < t);
        }
        if (rank < FAN2) d_cols2[rank] = t;
    }
}

// Build ids1[B*25] and ids2[B*250]
__global__ void build_ids_kernel(const int* __restrict__ ids,
                                 const int* __restrict__ adj) {
    int i = blockIdx.x * blockDim.x + threadIdx.x;
    if (i >= M1) return;
    int b = i / FAN1, s = i - b * FAN1;
    int id0 = ids[b];
    int id1 = adj[(size_t)id0 * MAXDEG + d_cols1[s]];
    d_ids1[i] = id1;
    const int* arow = adj + (size_t)id1 * MAXDEG;
    #pragma unroll
    for (int j = 0; j < FAN2; j++) {
        d_ids2[(size_t)i * FAN2 + j] = arow[d_cols2[j]];
    }
}

// mean over NS rows of src (indexed via idx, or contiguous if idx==null)
template <int NS>
__global__ void mean_rows_kernel(const float* __restrict__ src,
                                 const int* __restrict__ idx,
                                 float* __restrict__ out) {
    __shared__ int sidx[NS];
    int row = blockIdx.x;
    int t = threadIdx.x;  // 256 = DFEAT
    if (t < NS) sidx[t] = idx ? idx[(size_t)row * NS + t] : row * NS + t;
    __syncthreads();
    float s = 0.f;
    #pragma unroll
    for (int j = 0; j < NS; j++)
        s += src[(size_t)sidx[j] * DFEAT + t];
    out[(size_t)row * DFEAT + t] = s * (1.0f / NS);
}

// one-shot transpose of the 4 weight matrices [128,256] -> [256,128]
__global__ void transpose_w_kernel(const float* __restrict__ W1x,
                                   const float* __restrict__ W1n,
                                   const float* __restrict__ W2x,
                                   const float* __restrict__ W2n) {
    int m = blockIdx.y;
    const float* W = (m == 0) ? W1x : (m == 1) ? W1n : (m == 2) ? W2x : W2n;
    float* O = d_Wt + (size_t)m * DFEAT * OUTD;
    int i = blockIdx.x * blockDim.x + threadIdx.x;
    if (i < OUTD * DFEAT) {
        int c = i >> 8;      // /256
        int k = i & 255;
        O[k * OUTD + c] = W[i];
    }
}

// Fused (gather-)GEMM: C[row, coloff + c] = act( sum_k A[row,k] * W[c,k] + b[c] )
// A row source: gidx ? Asrc[gidx[row]] : Asrc[row].  Wt is [256][128] transposed.
// BM=64 rows/block, 256 threads, N=128 cols, K=256. M must be multiple of 64.
#define GBM 64
__global__ __launch_bounds__(256, 1)
void gemm_fused_kernel(const float* __restrict__ Asrc,
                       const int* __restrict__ gidx,
                       const float* __restrict__ Wt,
                       const float* __restrict__ bias,
                       float* __restrict__ C,
                       int coloff, int do_relu) {
    extern __shared__ float sm[];
    float* As = sm;                       // [64][256]
    float* Ws = sm + GBM * DFEAT;         // [256][128]
    __shared__ int rowidx[GBM];

    int t = threadIdx.x;
    int row0 = blockIdx.x * GBM;

    if (t < GBM) rowidx[t] = gidx ? gidx[row0 + t] : (row0 + t);

    // load transposed weights: 256*128 floats = 8192 float4 / 256 thr = 32 each
    {
        const float4* Wt4 = (const float4*)Wt;
        float4* Ws4 = (float4*)Ws;
        #pragma unroll
        for (int i = 0; i < 32; i++)
            Ws4[t + i * 256] = Wt4[t + i * 256];
    }
    __syncthreads();

    // load A tile: 64 rows * 64 float4 = 4096 float4 / 256 thr = 16 each
    #pragma unroll
    for (int i = 0; i < 16; i++) {
        int idx = t + i * 256;
        int r  = idx >> 6;
        int k4 = idx & 63;
        const float4* srow = (const float4*)(Asrc + (size_t)rowidx[r] * DFEAT);
        ((float4*)(As + r * DFEAT))[k4] = srow[k4];
    }
    __syncthreads();

    int warp = t >> 5;   // 0..7 -> base row
    int lane = t & 31;   // -> col group (4 cols)
    int c0 = lane * 4;

    float acc[8][4];
    #pragma unroll
    for (int i = 0; i < 8; i++)
        #pragma unroll
        for (int j = 0; j < 4; j++) acc[i][j] = 0.f;

    #pragma unroll 2
    for (int kk = 0; kk < DFEAT; kk += 4) {
        float4 wv0 = *(const float4*)(Ws + (kk + 0) * OUTD + c0);
        float4 wv1 = *(const float4*)(Ws + (kk + 1) * OUTD + c0);
        float4 wv2 = *(const float4*)(Ws + (kk + 2) * OUTD + c0);
        float4 wv3 = *(const float4*)(Ws + (kk + 3) * OUTD + c0);
        #pragma unroll
        for (int i = 0; i < 8; i++) {
            float4 av = *(const float4*)(As + (warp + i * 8) * DFEAT + kk);
            acc[i][0] += av.x * wv0.x + av.y * wv1.x + av.z * wv2.x + av.w * wv3.x;
            acc[i][1] += av.x * wv0.y + av.y * wv1.y + av.z * wv2.y + av.w * wv3.y;
            acc[i][2] += av.x * wv0.z + av.y * wv1.z + av.z * wv2.z + av.w * wv3.z;
            acc[i][3] += av.x * wv0.w + av.y * wv1.w + av.z * wv2.w + av.w * wv3.w;
        }
    }

    float4 bv = *(const float4*)(bias + c0);
    #pragma unroll
    for (int i = 0; i < 8; i++) {
        float4 o;
        o.x = acc[i][0] + bv.x;
        o.y = acc[i][1] + bv.y;
        o.z = acc[i][2] + bv.z;
        o.w = acc[i][3] + bv.w;
        if (do_relu) {
            o.x = fmaxf(o.x, 0.f); o.y = fmaxf(o.y, 0.f);
            o.z = fmaxf(o.z, 0.f); o.w = fmaxf(o.w, 0.f);
        }
        size_t r = (size_t)(row0 + warp + i * 8);
        *(float4*)(C + r * (2 * OUTD) + coloff + c0) = o;
    }
}

// ---------------- host launcher ----------------
extern "C" void kernel_launch(void* const* d_in, const int* in_sizes, int n_in,
                              void* d_out, int out_size) {
    const int*   ids   = (const int*)d_in[0];
    const int*   adj   = (const int*)d_in[1];
    const float* feats = (const float*)d_in[2];
    const float* W1x   = (const float*)d_in[3];
    const float* b1x   = (const float*)d_in[4];
    const float* W1n   = (const float*)d_in[5];
    const float* b1n   = (const float*)d_in[6];
    const float* W2x   = (const float*)d_in[7];
    const float* b2x   = (const float*)d_in[8];
    const float* W2n   = (const float*)d_in[9];
    const float* b2n   = (const float*)d_in[10];
    float* out = (float*)d_out;

    // resolve scratch symbols (host API, capture-safe)
    float *p_m2, *p_z1, *p_m1, *p_z0, *p_m3, *p_Wt;
    int *p_ids1, *p_ids2;
    cudaGetSymbolAddress((void**)&p_m2,  d_m2);
    cudaGetSymbolAddress((void**)&p_z1,  d_z1);
    cudaGetSymbolAddress((void**)&p_m1,  d_m1);
    cudaGetSymbolAddress((void**)&p_z0,  d_z0);
    cudaGetSymbolAddress((void**)&p_m3,  d_m3);
    cudaGetSymbolAddress((void**)&p_Wt,  d_Wt);
    cudaGetSymbolAddress((void**)&p_ids1, d_ids1);
    cudaGetSymbolAddress((void**)&p_ids2, d_ids2);

    const int GEMM_SMEM = (GBM * DFEAT + DFEAT * OUTD) * sizeof(float); // 196608
    cudaFuncSetAttribute(gemm_fused_kernel,
                         cudaFuncAttributeMaxDynamicSharedMemorySize, GEMM_SMEM);

    // 1. permutations (threefry, partitionable semantics, bits1 ^ bits2)
    setup_perm_kernel<<<1, 128>>>();
    // 2. weight transpose
    transpose_w_kernel<<<dim3(128, 4), 256>>>(W1x, W1n, W2x, W2n);
    // 3. neighbor id tables
    build_ids_kernel<<<(M1 + 255) / 256, 256>>>(ids, adj);
    // 4. m2 = mean_{fan2}(feats[ids2])   [25600,256]  (the memory-bound core)
    mean_rows_kernel<FAN2><<<M1, DFEAT>>>(feats, p_ids2, p_m2);
    // 5. z1 = relu([feats[ids1]@W1x^T + b1x | m2@W1n^T + b1n])   [25600,256]
    gemm_fused_kernel<<<M1 / GBM, 256, GEMM_SMEM>>>(feats, p_ids1, p_Wt + 0 * DFEAT * OUTD, b1x, p_z1, 0,    1);
    gemm_fused_kernel<<<M1 / GBM, 256, GEMM_SMEM>>>(p_m2,  nullptr, p_Wt + 1 * DFEAT * OUTD, b1n, p_z1, OUTD, 1);
    // 6. m1 = mean_{fan1}(feats[ids1])   [1024,256]
    mean_rows_kernel<FAN1><<<BATCH, DFEAT>>>(feats, p_ids1, p_m1);
    // 7. z0 = relu([feats[ids]@W1x^T + b1x | m1@W1n^T + b1n])   [1024,256]
    gemm_fused_kernel<<<BATCH / GBM, 256, GEMM_SMEM>>>(feats, ids,    p_Wt + 0 * DFEAT * OUTD, b1x, p_z0, 0,    1);
    gemm_fused_kernel<<<BATCH / GBM, 256, GEMM_SMEM>>>(p_m1, nullptr, p_Wt + 1 * DFEAT * OUTD, b1n, p_z0, OUTD, 1);
    // 8. m3 = mean_{fan1}(z1)   [1024,256]
    mean_rows_kernel<FAN1><<<BATCH, DFEAT>>>(p_z1, nullptr, p_m3);
    // 9. out = [z0@W2x^T + b2x | m3@W2n^T + b2n]   [1024,256], no relu
    gemm_fused_kernel<<<BATCH / GBM, 256, GEMM_SMEM>>>(p_z0, nullptr, p_Wt + 2 * DFEAT * OUTD, b2x, out, 0,    0);
    gemm_fused_kernel<<<BATCH / GBM, 256, GEMM_SMEM>>>(p_m3, nullptr, p_Wt + 3 * DFEAT * OUTD, b2n, out, OUTD, 0);
}

// round 5
// speedup vs baseline: 1.1355x; 1.1355x over previous
#include <cuda_runtime.h>
#include <cstdint>
#include <cstddef>

// ---------------- problem constants ----------------
#define NNODES   100000
#define DFEAT    256
#define MAXDEG   128
#define BATCH    1024
#define FAN1     25
#define FAN2     10
#define OUTD     128           // per-branch output
#define M1       (BATCH*FAN1)          // 25600
#define M2       (BATCH*FAN1*FAN2)     // 256000

// ---------------- scratch (device globals; no allocation APIs) ----------------
__device__ int      d_cols1[FAN1];
__device__ int      d_cols2[FAN2];
__device__ int      d_ids1[M1];
__device__ int      d_ids2[M2];
__device__ float    d_m2[M1 * DFEAT];     // mean over fan2 of feats[ids2]
__device__ float    d_z1[M1 * DFEAT];     // layer-1 output for ids1 rows
__device__ float    d_m1[BATCH * DFEAT];  // mean over fan1 of feats[ids1]
__device__ float    d_z0[BATCH * DFEAT];  // layer-1 output for ids rows
__device__ float    d_m3[BATCH * DFEAT];  // mean over fan1 of z1
__device__ uint32_t d_Wh[4 * OUTD * DFEAT]; // tf32 hi of weights, [n][k] layout
__device__ uint32_t d_Wl[4 * OUTD * DFEAT]; // tf32 lo

// ---------------- threefry2x32 (JAX-exact, 20 rounds) ----------------
__device__ __forceinline__ uint32_t rotl32(uint32_t v, int r) {
    return (v << r) | (v >> (32 - r));
}

__device__ __forceinline__ void tf2x32(uint32_t k0, uint32_t k1,
                                       uint32_t x0, uint32_t x1,
                                       uint32_t& y0, uint32_t& y1) {
    uint32_t ks0 = k0, ks1 = k1, ks2 = k0 ^ k1 ^ 0x1BD11BDAu;
    x0 += ks0; x1 += ks1;
    const int r0[4] = {13, 15, 26, 6};
    const int r1[4] = {17, 29, 16, 24};
#define TF_G(RR) { x0 += x1; x1 = rotl32(x1, RR[0]); x1 ^= x0; \
                   x0 += x1; x1 = rotl32(x1, RR[1]); x1 ^= x0; \
                   x0 += x1; x1 = rotl32(x1, RR[2]); x1 ^= x0; \
                   x0 += x1; x1 = rotl32(x1, RR[3]); x1 ^= x0; }
    TF_G(r0); x0 += ks1; x1 += ks2 + 1u;
    TF_G(r1); x0 += ks2; x1 += ks0 + 2u;
    TF_G(r0); x0 += ks0; x1 += ks1 + 3u;
    TF_G(r1); x0 += ks1; x1 += ks2 + 4u;
    TF_G(r0); x0 += ks2; x1 += ks0 + 5u;
#undef TF_G
    y0 = x0; y1 = x1;
}

// jax.random.permutation(k, 128) for k1,k2 = split(key(42)),
// partitionable semantics; random_bits(32) = bits1 ^ bits2 (VERIFIED round 4)
__global__ void setup_perm_kernel() {
    int t = threadIdx.x;  // 128 threads
    uint32_t k1a, k1b, k2a, k2b;
    tf2x32(0u, 42u, 0u, 0u, k1a, k1b);   // k1 = block (0,0)
    tf2x32(0u, 42u, 0u, 1u, k2a, k2b);   // k2 = block (0,1)
    uint32_t s1a, s1b, s2a, s2b;
    tf2x32(k1a, k1b, 0u, 1u, s1a, s1b);  // subkey of shuffle round for k1
    tf2x32(k2a, k2b, 0u, 1u, s2a, s2b);  // subkey for k2

    __shared__ uint32_t keys[MAXDEG];
    uint32_t b1, b2;

    tf2x32(s1a, s1b, 0u, (uint32_t)t, b1, b2);
    keys[t] = b1 ^ b2;
    __syncthreads();
    {
        uint32_t me = keys[t];
        int rank = 0;
        #pragma unroll 8
        for (int j = 0; j < MAXDEG; j++) {
            uint32_t kj = keys[j];
            rank += (kj < me) || (kj == me && j < t);
        }
        if (rank < FAN1) d_cols1[rank] = t;
    }
    __syncthreads();

    tf2x32(s2a, s2b, 0u, (uint32_t)t, b1, b2);
    keys[t] = b1 ^ b2;
    __syncthreads();
    {
        uint32_t me = keys[t];
        int rank = 0;
        #pragma unroll 8
        for (int j = 0; j < MAXDEG; j++) {
            uint32_t kj = keys[j];
            rank += (kj < me) || (kj == me && j < t);
        }
        if (rank < FAN2) d_cols2[rank] = t;
    }
}

// Build ids1[B*25] and ids2[B*250]
__global__ void build_ids_kernel(const int* __restrict__ ids,
                                 const int* __restrict__ adj) {
    int i = blockIdx.x * blockDim.x + threadIdx.x;
    if (i >= M1) return;
    int b = i / FAN1, s = i - b * FAN1;
    int id0 = ids[b];
    int id1 = adj[(size_t)id0 * MAXDEG + d_cols1[s]];
    d_ids1[i] = id1;
    const int* arow = adj + (size_t)id1 * MAXDEG;
    #pragma unroll
    for (int j = 0; j < FAN2; j++) {
        d_ids2[(size_t)i * FAN2 + j] = arow[d_cols2[j]];
    }
}

// mean over NS rows of src (indexed via idx, or contiguous if idx==null)
template <int NS>
__global__ void mean_rows_kernel(const float* __restrict__ src,
                                 const int* __restrict__ idx,
                                 float* __restrict__ out) {
    __shared__ int sidx[NS];
    int row = blockIdx.x;
    int t = threadIdx.x;  // 256 = DFEAT
    if (t < NS) sidx[t] = idx ? idx[(size_t)row * NS + t] : row * NS + t;
    __syncthreads();
    float s = 0.f;
    #pragma unroll
    for (int j = 0; j < NS; j++)
        s += src[(size_t)sidx[j] * DFEAT + t];
    out[(size_t)row * DFEAT + t] = s * (1.0f / NS);
}

// ---------------- tf32 helpers ----------------
__device__ __forceinline__ uint32_t f2tf32(float x) {
    uint32_t r;
    asm("cvt.rna.tf32.f32 %0, %1;" : "=r"(r) : "f"(x));
    return r;
}

#define MMA_TF32(d, a0, a1, a2, a3, b0, b1) \
    asm volatile( \
        "mma.sync.aligned.m16n8k8.row.col.f32.tf32.tf32.f32 " \
        "{%0,%1,%2,%3}, {%4,%5,%6,%7}, {%8,%9}, {%0,%1,%2,%3};" \
        : "+f"((d)[0]), "+f"((d)[1]), "+f"((d)[2]), "+f"((d)[3]) \
        : "r"(a0), "r"(a1), "r"(a2), "r"(a3), "r"(b0), "r"(b1))

// one-shot tf32 hi/lo split of the 4 weight matrices, kept in [n][k] layout
__global__ void split_w_kernel(const float* __restrict__ W1x,
                               const float* __restrict__ W1n,
                               const float* __restrict__ W2x,
                               const float* __restrict__ W2n) {
    int m = blockIdx.y;
    const float* W = (m == 0) ? W1x : (m == 1) ? W1n : (m == 2) ? W2x : W2n;
    int i = blockIdx.x * blockDim.x + threadIdx.x;
    if (i < OUTD * DFEAT) {
        float w = W[i];
        uint32_t h = f2tf32(w);
        float lo = w - __uint_as_float(h);
        uint32_t l = f2tf32(lo);
        d_Wh[(size_t)m * OUTD * DFEAT + i] = h;
        d_Wl[(size_t)m * OUTD * DFEAT + i] = l;
    }
}

// ---------------- tensor-core fused gather-GEMM (3xTF32) ----------------
// C[row, coloff+c] = act( sum_k A[row,k] * W[c,k] + b[c] ),  row gathered via gidx.
// Block: 256 threads (8 warps, 2x4 warp grid), BM=64, BN=128, K=256 in 4 chunks.
// smem: Ah/Al [64][68], Bh/Bl [128][68] (stride 68 == 4 mod 32: conflict-free frags)
#define GBM   64
#define KCH   64
#define APAD  68
#define SM_AH 0
#define SM_AL (GBM * APAD)
#define SM_BH (2 * GBM * APAD)
#define SM_BL (2 * GBM * APAD + OUTD * APAD)
#define GEMM_SMEM_WORDS (2 * GBM * APAD + 2 * OUTD * APAD)   // 26112 words = 104448 B

__global__ __launch_bounds__(256, 2)
void gemm_tc_kernel(const float* __restrict__ Asrc,
                    const int* __restrict__ gidx,
                    const uint32_t* __restrict__ Wh,
                    const uint32_t* __restrict__ Wl,
                    const float* __restrict__ bias,
                    float* __restrict__ C,
                    int coloff, int do_relu) {
    extern __shared__ uint32_t smx[];
    uint32_t* Ash = smx + SM_AH;
    uint32_t* Asl = smx + SM_AL;
    uint32_t* Bsh = smx + SM_BH;
    uint32_t* Bsl = smx + SM_BL;
    __shared__ int rowidx[GBM];

    int t = threadIdx.x;
    int row0 = blockIdx.x * GBM;
    if (t < GBM) rowidx[t] = gidx ? gidx[row0 + t] : (row0 + t);
    __syncthreads();

    int wid = t >> 5, lane = t & 31;
    int wm = wid & 1;        // 0..1 -> 32-row slab
    int wn = wid >> 1;       // 0..3 -> 32-col slab
    int qp = lane >> 2;      // 0..7
    int qi = lane & 3;       // 0..3

    float acc[2][4][4];
    #pragma unroll
    for (int mt = 0; mt < 2; mt++)
        #pragma unroll
        for (int nt = 0; nt < 4; nt++)
            #pragma unroll
            for (int j = 0; j < 4; j++) acc[mt][nt][j] = 0.f;

    for (int kc = 0; kc < 4; kc++) {
        // ---- load + split A chunk: 64 rows x 64 k (1024 float4 / 256 thr = 4 each)
        #pragma unroll
        for (int i = 0; i < 4; i++) {
            int idx = t + i * 256;
            int r  = idx >> 4;
            int k4 = idx & 15;
            const float4 v = *(const float4*)(Asrc + (size_t)rowidx[r] * DFEAT
                                              + kc * KCH + k4 * 4);
            uint4 h, l;
            h.x = f2tf32(v.x); l.x = f2tf32(v.x - __uint_as_float(h.x));
            h.y = f2tf32(v.y); l.y = f2tf32(v.y - __uint_as_float(h.y));
            h.z = f2tf32(v.z); l.z = f2tf32(v.z - __uint_as_float(h.z));
            h.w = f2tf32(v.w); l.w = f2tf32(v.w - __uint_as_float(h.w));
            *(uint4*)(Ash + r * APAD + k4 * 4) = h;
            *(uint4*)(Asl + r * APAD + k4 * 4) = l;
        }
        // ---- load B chunk (pre-split): 128 rows x 64 k (2048 float4 -> 8 each)
        #pragma unroll
        for (int i = 0; i < 8; i++) {
            int idx = t + i * 256;
            int r  = idx >> 4;
            int k4 = idx & 15;
            *(uint4*)(Bsh + r * APAD + k4 * 4) =
                *(const uint4*)(Wh + (size_t)r * DFEAT + kc * KCH + k4 * 4);
            *(uint4*)(Bsl + r * APAD + k4 * 4) =
                *(const uint4*)(Wl + (size_t)r * DFEAT + kc * KCH + k4 * 4);
        }
        __syncthreads();

        #pragma unroll
        for (int kk = 0; kk < KCH; kk += 8) {
            uint32_t ah[2][4], al[2][4];
            #pragma unroll
            for (int mt = 0; mt < 2; mt++) {
                int rm = wm * 32 + mt * 16 + qp;
                ah[mt][0] = Ash[rm * APAD + kk + qi];
                ah[mt][1] = Ash[(rm + 8) * APAD + kk + qi];
                ah[mt][2] = Ash[rm * APAD + kk + qi + 4];
                ah[mt][3] = Ash[(rm + 8) * APAD + kk + qi + 4];
                al[mt][0] = Asl[rm * APAD + kk + qi];
                al[mt][1] = Asl[(rm + 8) * APAD + kk + qi];
                al[mt][2] = Asl[rm * APAD + kk + qi + 4];
                al[mt][3] = Asl[(rm + 8) * APAD + kk + qi + 4];
            }
            #pragma unroll
            for (int nt = 0; nt < 4; nt++) {
                int nb = wn * 32 + nt * 8 + qp;
                uint32_t bh0 = Bsh[nb * APAD + kk + qi];
                uint32_t bh1 = Bsh[nb * APAD + kk + qi + 4];
                uint32_t bl0 = Bsl[nb * APAD + kk + qi];
                uint32_t bl1 = Bsl[nb * APAD + kk + qi + 4];
                #pragma unroll
                for (int mt = 0; mt < 2; mt++) {
                    MMA_TF32(acc[mt][nt], ah[mt][0], ah[mt][1], ah[mt][2], ah[mt][3], bh0, bh1);
                    MMA_TF32(acc[mt][nt], ah[mt][0], ah[mt][1], ah[mt][2], ah[mt][3], bl0, bl1);
                    MMA_TF32(acc[mt][nt], al[mt][0], al[mt][1], al[mt][2], al[mt][3], bh0, bh1);
                }
            }
        }
        __syncthreads();
    }

    // ---- epilogue: bias + optional relu, write to C (row stride 2*OUTD)
    #pragma unroll
    for (int nt = 0; nt < 4; nt++) {
        int col = wn * 32 + nt * 8 + 2 * qi;
        float bx = bias[col], by = bias[col + 1];
        #pragma unroll
        for (int mt = 0; mt < 2; mt++) {
            int r0 = row0 + wm * 32 + mt * 16 + qp;
            float v0 = acc[mt][nt][0] + bx;
            float v1 = acc[mt][nt][1] + by;
            float v2 = acc[mt][nt][2] + bx;
            float v3 = acc[mt][nt][3] + by;
            if (do_relu) {
                v0 = fmaxf(v0, 0.f); v1 = fmaxf(v1, 0.f);
                v2 = fmaxf(v2, 0.f); v3 = fmaxf(v3, 0.f);
            }
            *(float2*)(C + (size_t)r0 * (2 * OUTD) + coloff + col)       = make_float2(v0, v1);
            *(float2*)(C + (size_t)(r0 + 8) * (2 * OUTD) + coloff + col) = make_float2(v2, v3);
        }
    }
}

// ---------------- host launcher ----------------
extern "C" void kernel_launch(void* const* d_in, const int* in_sizes, int n_in,
                              void* d_out, int out_size) {
    const int*   ids   = (const int*)d_in[0];
    const int*   adj   = (const int*)d_in[1];
    const float* feats = (const float*)d_in[2];
    const float* W1x   = (const float*)d_in[3];
    const float* b1x   = (const float*)d_in[4];
    const float* W1n   = (const float*)d_in[5];
    const float* b1n   = (const float*)d_in[6];
    const float* W2x   = (const float*)d_in[7];
    const float* b2x   = (const float*)d_in[8];
    const float* W2n   = (const float*)d_in[9];
    const float* b2n   = (const float*)d_in[10];
    float* out = (float*)d_out;

    float *p_m2, *p_z1, *p_m1, *p_z0, *p_m3;
    uint32_t *p_Wh, *p_Wl;
    int *p_ids1, *p_ids2;
    cudaGetSymbolAddress((void**)&p_m2,  d_m2);
    cudaGetSymbolAddress((void**)&p_z1,  d_z1);
    cudaGetSymbolAddress((void**)&p_m1,  d_m1);
    cudaGetSymbolAddress((void**)&p_z0,  d_z0);
    cudaGetSymbolAddress((void**)&p_m3,  d_m3);
    cudaGetSymbolAddress((void**)&p_Wh,  d_Wh);
    cudaGetSymbolAddress((void**)&p_Wl,  d_Wl);
    cudaGetSymbolAddress((void**)&p_ids1, d_ids1);
    cudaGetSymbolAddress((void**)&p_ids2, d_ids2);

    const int GEMM_SMEM = GEMM_SMEM_WORDS * 4;   // 104448 bytes
    cudaFuncSetAttribute(gemm_tc_kernel,
                         cudaFuncAttributeMaxDynamicSharedMemorySize, GEMM_SMEM);

    const size_t WSZ = (size_t)OUTD * DFEAT;   // per-matrix words

    // 1. permutations (threefry, partitionable, bits1 ^ bits2)
    setup_perm_kernel<<<1, 128>>>();
    // 2. weight tf32 hi/lo split
    split_w_kernel<<<dim3(128, 4), 256>>>(W1x, W1n, W2x, W2n);
    // 3. neighbor id tables
    build_ids_kernel<<<(M1 + 255) / 256, 256>>>(ids, adj);
    // 4. m2 = mean_{fan2}(feats[ids2])   [25600,256]
    mean_rows_kernel<FAN2><<<M1, DFEAT>>>(feats, p_ids2, p_m2);
    // 5. z1 = relu([feats[ids1]@W1x^T + b1x | m2@W1n^T + b1n])   [25600,256]
    gemm_tc_kernel<<<M1 / GBM, 256, GEMM_SMEM>>>(feats, p_ids1, p_Wh + 0 * WSZ, p_Wl + 0 * WSZ, b1x, p_z1, 0,    1);
    gemm_tc_kernel<<<M1 / GBM, 256, GEMM_SMEM>>>(p_m2,  nullptr, p_Wh + 1 * WSZ, p_Wl + 1 * WSZ, b1n, p_z1, OUTD, 1);
    // 6. m1 = mean_{fan1}(feats[ids1])   [1024,256]
    mean_rows_kernel<FAN1><<<BATCH, DFEAT>>>(feats, p_ids1, p_m1);
    // 7. z0 = relu([feats[ids]@W1x^T + b1x | m1@W1n^T + b1n])   [1024,256]
    gemm_tc_kernel<<<BATCH / GBM, 256, GEMM_SMEM>>>(feats, ids,    p_Wh + 0 * WSZ, p_Wl + 0 * WSZ, b1x, p_z0, 0,    1);
    gemm_tc_kernel<<<BATCH / GBM, 256, GEMM_SMEM>>>(p_m1, nullptr, p_Wh + 1 * WSZ, p_Wl + 1 * WSZ, b1n, p_z0, OUTD, 1);
    // 8. m3 = mean_{fan1}(z1)   [1024,256]
    mean_rows_kernel<FAN1><<<BATCH, DFEAT>>>(p_z1, nullptr, p_m3);
    // 9. out = [z0@W2x^T + b2x | m3@W2n^T + b2n]   [1024,256], no relu
    gemm_tc_kernel<<<BATCH / GBM, 256, GEMM_SMEM>>>(p_z0, nullptr, p_Wh + 2 * WSZ, p_Wl + 2 * WSZ, b2x, out, 0,    0);
    gemm_tc_kernel<<<BATCH / GBM, 256, GEMM_SMEM>>>(p_m3, nullptr, p_Wh + 3 * WSZ, p_Wl + 3 * WSZ, b2n, out, OUTD, 0);
}

// round 6
// speedup vs baseline: 2.2469x; 1.9787x over previous
#include <cuda_runtime.h>
#include <cuda_fp16.h>
#include <cstdint>
#include <cstddef>

// ---------------- problem constants ----------------
#define NNODES   100000
#define DFEAT    256
#define MAXDEG   128
#define BATCH    1024
#define FAN1     25
#define FAN2     10
#define OUTD     128           // per-branch output
#define M1       (BATCH*FAN1)          // 25600
#define M2       (BATCH*FAN1*FAN2)     // 256000
#define WSZH     (OUTD * DFEAT / 2)    // half2 words per weight matrix = 16384

// ---------------- scratch (device globals; no allocation APIs) ----------------
__device__ int      d_cols1[FAN1];
__device__ int      d_cols2[FAN2];
__device__ int      d_ids1[M1];
__device__ int      d_ids2[M2];
__device__ float    d_m2[M1 * DFEAT];     // mean over fan2 of feats[ids2]
__device__ float    d_z1[M1 * DFEAT];     // layer-1 output for ids1 rows
__device__ float    d_m1[BATCH * DFEAT];  // mean over fan1 of feats[ids1]
__device__ float    d_z0[BATCH * DFEAT];  // layer-1 output for ids rows
__device__ float    d_m3[BATCH * DFEAT];  // mean over fan1 of z1
__device__ uint32_t d_Whh[4 * WSZH];      // fp16 hi of weights, [n][k] half2-packed
__device__ uint32_t d_Wll[4 * WSZH];      // fp16 lo

// ---------------- threefry2x32 (JAX-exact, 20 rounds) ----------------
__device__ __forceinline__ uint32_t rotl32(uint32_t v, int r) {
    return (v << r) | (v >> (32 - r));
}

__device__ __forceinline__ void tf2x32(uint32_t k0, uint32_t k1,
                                       uint32_t x0, uint32_t x1,
                                       uint32_t& y0, uint32_t& y1) {
    uint32_t ks0 = k0, ks1 = k1, ks2 = k0 ^ k1 ^ 0x1BD11BDAu;
    x0 += ks0; x1 += ks1;
    const int r0[4] = {13, 15, 26, 6};
    const int r1[4] = {17, 29, 16, 24};
#define TF_G(RR) { x0 += x1; x1 = rotl32(x1, RR[0]); x1 ^= x0; \
                   x0 += x1; x1 = rotl32(x1, RR[1]); x1 ^= x0; \
                   x0 += x1; x1 = rotl32(x1, RR[2]); x1 ^= x0; \
                   x0 += x1; x1 = rotl32(x1, RR[3]); x1 ^= x0; }
    TF_G(r0); x0 += ks1; x1 += ks2 + 1u;
    TF_G(r1); x0 += ks2; x1 += ks0 + 2u;
    TF_G(r0); x0 += ks0; x1 += ks1 + 3u;
    TF_G(r1); x0 += ks1; x1 += ks2 + 4u;
    TF_G(r0); x0 += ks2; x1 += ks0 + 5u;
#undef TF_G
    y0 = x0; y1 = x1;
}

// jax.random.permutation(k, 128) for k1,k2 = split(key(42)),
// partitionable semantics; random_bits(32) = bits1 ^ bits2 (VERIFIED round 4)
__global__ void setup_perm_kernel() {
    int t = threadIdx.x;  // 128 threads
    uint32_t k1a, k1b, k2a, k2b;
    tf2x32(0u, 42u, 0u, 0u, k1a, k1b);
    tf2x32(0u, 42u, 0u, 1u, k2a, k2b);
    uint32_t s1a, s1b, s2a, s2b;
    tf2x32(k1a, k1b, 0u, 1u, s1a, s1b);
    tf2x32(k2a, k2b, 0u, 1u, s2a, s2b);

    __shared__ uint32_t keys[MAXDEG];
    uint32_t b1, b2;

    tf2x32(s1a, s1b, 0u, (uint32_t)t, b1, b2);
    keys[t] = b1 ^ b2;
    __syncthreads();
    {
        uint32_t me = keys[t];
        int rank = 0;
        #pragma unroll 8
        for (int j = 0; j < MAXDEG; j++) {
            uint32_t kj = keys[j];
            rank += (kj < me) || (kj == me && j < t);
        }
        if (rank < FAN1) d_cols1[rank] = t;
    }
    __syncthreads();

    tf2x32(s2a, s2b, 0u, (uint32_t)t, b1, b2);
    keys[t] = b1 ^ b2;
    __syncthreads();
    {
        uint32_t me = keys[t];
        int rank = 0;
        #pragma unroll 8
        for (int j = 0; j < MAXDEG; j++) {
            uint32_t kj = keys[j];
            rank += (kj < me) || (kj == me && j < t);
        }
        if (rank < FAN2) d_cols2[rank] = t;
    }
}

// Build ids1[B*25] and ids2[B*250]
__global__ void build_ids_kernel(const int* __restrict__ ids,
                                 const int* __restrict__ adj) {
    int i = blockIdx.x * blockDim.x + threadIdx.x;
    if (i >= M1) return;
    int b = i / FAN1, s = i - b * FAN1;
    int id0 = ids[b];
    int id1 = adj[(size_t)id0 * MAXDEG + d_cols1[s]];
    d_ids1[i] = id1;
    const int* arow = adj + (size_t)id1 * MAXDEG;
    #pragma unroll
    for (int j = 0; j < FAN2; j++) {
        d_ids2[(size_t)i * FAN2 + j] = arow[d_cols2[j]];
    }
}

// mean over NS rows, 4 output rows per block, float4 lanes (256 threads)
template <int NS>
__global__ void mean4_kernel(const float* __restrict__ src,
                             const int* __restrict__ idx,
                             float* __restrict__ out) {
    __shared__ int sidx[4][NS];
    int t = threadIdx.x;
    int row0 = blockIdx.x * 4;
    if (t < 4 * NS) {
        int rr = t / NS, jj = t - rr * NS;
        sidx[rr][jj] = idx ? idx[(size_t)(row0 + rr) * NS + jj]
                           : (row0 + rr) * NS + jj;
    }
    __syncthreads();
    int rr = t >> 6;
    int c4 = (t & 63) * 4;
    float4 s = make_float4(0.f, 0.f, 0.f, 0.f);
    #pragma unroll
    for (int j = 0; j < NS; j++) {
        const float4 v = *(const float4*)(src + (size_t)sidx[rr][j] * DFEAT + c4);
        s.x += v.x; s.y += v.y; s.z += v.z; s.w += v.w;
    }
    const float inv = 1.0f / NS;
    s.x *= inv; s.y *= inv; s.z *= inv; s.w *= inv;
    *(float4*)(out + (size_t)(row0 + rr) * DFEAT + c4) = s;
}

// one-shot fp16 hi/lo split of the 4 weight matrices, [n][k] half2-packed
__global__ void split_w_kernel(const float* __restrict__ W1x,
                               const float* __restrict__ W1n,
                               const float* __restrict__ W2x,
                               const float* __restrict__ W2n) {
    int m = blockIdx.y;
    const float* W = (m == 0) ? W1x : (m == 1) ? W1n : (m == 2) ? W2x : W2n;
    int i = blockIdx.x * blockDim.x + threadIdx.x;   // half2-pair index
    if (i < WSZH) {
        float w0 = W[2 * i], w1 = W[2 * i + 1];
        __half h0 = __float2half_rn(w0), h1 = __float2half_rn(w1);
        float l0 = w0 - __half2float(h0);
        float l1 = w1 - __half2float(h1);
        __half2 hh = __halves2half2(h0, h1);
        __half2 ll = __floats2half2_rn(l0, l1);
        d_Whh[(size_t)m * WSZH + i] = *(uint32_t*)&hh;
        d_Wll[(size_t)m * WSZH + i] = *(uint32_t*)&ll;
    }
}

#define MMA_F16(d, a0, a1, a2, a3, b0, b1) \
    asm volatile( \
        "mma.sync.aligned.m16n8k16.row.col.f32.f16.f16.f32 " \
        "{%0,%1,%2,%3}, {%4,%5,%6,%7}, {%8,%9}, {%0,%1,%2,%3};" \
        : "+f"((d)[0]), "+f"((d)[1]), "+f"((d)[2]), "+f"((d)[3]) \
        : "r"(a0), "r"(a1), "r"(a2), "r"(a3), "r"(b0), "r"(b1))

// ---------------- tensor-core fused gather-GEMM (fp16 3-way split) ----------------
// gridDim.y = 2 selects branch: (A-source, gather idx, weight matrix, bias, col half)
// C[row, b*128 + c] = act( sum_k A_b[row,k] * W_b[c,k] + bias_b[c] )
// Block: 256 thr (8 warps, 2x4), BM=64, BN=128, K=256 in 4 chunks of 64.
// smem half2-words, row stride 36 (== 4 mod 32: conflict-free fragments).
#define GBM   64
#define KCH   64
#define STR   36
#define SM_AH 0
#define SM_AL (GBM * STR)
#define SM_BH (2 * GBM * STR)
#define SM_BL (2 * GBM * STR + OUTD * STR)
#define GEMM_SMEM_WORDS (2 * GBM * STR + 2 * OUTD * STR)   // 13824 words = 55296 B

__global__ __launch_bounds__(256, 3)
void gemm_tc_kernel(const float* __restrict__ A0, const int* __restrict__ g0,
                    const float* __restrict__ A1, const int* __restrict__ g1,
                    int wsel0, int wsel1,
                    const float* __restrict__ bias0, const float* __restrict__ bias1,
                    float* __restrict__ C, int do_relu) {
    extern __shared__ uint32_t smx[];
    uint32_t* Ash = smx + SM_AH;
    uint32_t* Asl = smx + SM_AL;
    uint32_t* Bsh = smx + SM_BH;
    uint32_t* Bsl = smx + SM_BL;
    __shared__ int rowidx[GBM];

    int branch = blockIdx.y;
    const float* Asrc = branch ? A1 : A0;
    const int*   gidx = branch ? g1 : g0;
    const uint32_t* Wh = d_Whh + (size_t)(branch ? wsel1 : wsel0) * WSZH;
    const uint32_t* Wl = d_Wll + (size_t)(branch ? wsel1 : wsel0) * WSZH;
    const float* bias = branch ? bias1 : bias0;
    int coloff = branch * OUTD;

    int t = threadIdx.x;
    int row0 = blockIdx.x * GBM;
    if (t < GBM) rowidx[t] = gidx ? gidx[row0 + t] : (row0 + t);
    __syncthreads();

    int wid = t >> 5, lane = t & 31;
    int wm = wid & 1;        // 0..1 -> 32-row slab
    int wn = wid >> 1;       // 0..3 -> 32-col slab
    int qp = lane >> 2;      // 0..7
    int qi = lane & 3;       // 0..3

    float acc[2][4][4];
    #pragma unroll
    for (int mt = 0; mt < 2; mt++)
        #pragma unroll
        for (int nt = 0; nt < 4; nt++)
            #pragma unroll
            for (int j = 0; j < 4; j++) acc[mt][nt][j] = 0.f;

    for (int kc = 0; kc < 4; kc++) {
        // ---- A chunk: 64 rows x 64 k = 1024 float4 / 256 thr = 4 each; split to fp16
        #pragma unroll
        for (int i = 0; i < 4; i++) {
            int idx = t + i * 256;
            int r  = idx >> 4;
            int k4 = idx & 15;
            const float4 v = *(const float4*)(Asrc + (size_t)rowidx[r] * DFEAT
                                              + kc * KCH + k4 * 4);
            __half2 h01 = __floats2half2_rn(v.x, v.y);
            __half2 h23 = __floats2half2_rn(v.z, v.w);
            float2 f01 = __half22float2(h01);
            float2 f23 = __half22float2(h23);
            __half2 l01 = __floats2half2_rn(v.x - f01.x, v.y - f01.y);
            __half2 l23 = __floats2half2_rn(v.z - f23.x, v.w - f23.y);
            uint2 hw, lw;
            hw.x = *(uint32_t*)&h01; hw.y = *(uint32_t*)&h23;
            lw.x = *(uint32_t*)&l01; lw.y = *(uint32_t*)&l23;
            *(uint2*)(Ash + r * STR + k4 * 2) = hw;
            *(uint2*)(Asl + r * STR + k4 * 2) = lw;
        }
        // ---- B chunk (pre-split): 128 rows x 32 words = 1024 uint4 pairs -> 4 each
        #pragma unroll
        for (int i = 0; i < 4; i++) {
            int idx = t + i * 256;
            int r  = idx >> 3;
            int w4 = idx & 7;
            *(uint4*)(Bsh + r * STR + w4 * 4) =
                *(const uint4*)(Wh + (size_t)r * (DFEAT / 2) + kc * (KCH / 2) + w4 * 4);
            *(uint4*)(Bsl + r * STR + w4 * 4) =
                *(const uint4*)(Wl + (size_t)r * (DFEAT / 2) + kc * (KCH / 2) + w4 * 4);
        }
        __syncthreads();

        #pragma unroll
        for (int kk2 = 0; kk2 < KCH / 2; kk2 += 8) {   // one m16n8k16 per step
            uint32_t ah[2][4], al[2][4];
            #pragma unroll
            for (int mt = 0; mt < 2; mt++) {
                int rm = wm * 32 + mt * 16 + qp;
                ah[mt][0] = Ash[rm * STR + kk2 + qi];
                ah[mt][1] = Ash[(rm + 8) * STR + kk2 + qi];
                ah[mt][2] = Ash[rm * STR + kk2 + qi + 4];
                ah[mt][3] = Ash[(rm + 8) * STR + kk2 + qi + 4];
                al[mt][0] = Asl[rm * STR + kk2 + qi];
                al[mt][1] = Asl[(rm + 8) * STR + kk2 + qi];
                al[mt][2] = Asl[rm * STR + kk2 + qi + 4];
                al[mt][3] = Asl[(rm + 8) * STR + kk2 + qi + 4];
            }
            #pragma unroll
            for (int nt = 0; nt < 4; nt++) {
                int nb = wn * 32 + nt * 8 + qp;
                uint32_t bh0 = Bsh[nb * STR + kk2 + qi];
                uint32_t bh1 = Bsh[nb * STR + kk2 + qi + 4];
                uint32_t bl0 = Bsl[nb * STR + kk2 + qi];
                uint32_t bl1 = Bsl[nb * STR + kk2 + qi + 4];
                #pragma unroll
                for (int mt = 0; mt < 2; mt++) {
                    MMA_F16(acc[mt][nt], ah[mt][0], ah[mt][1], ah[mt][2], ah[mt][3], bh0, bh1);
                    MMA_F16(acc[mt][nt], ah[mt][0], ah[mt][1], ah[mt][2], ah[mt][3], bl0, bl1);
                    MMA_F16(acc[mt][nt], al[mt][0], al[mt][1], al[mt][2], al[mt][3], bh0, bh1);
                }
            }
        }
        __syncthreads();
    }

    // ---- epilogue: bias + optional relu, write to C (row stride 2*OUTD)
    #pragma unroll
    for (int nt = 0; nt < 4; nt++) {
        int col = wn * 32 + nt * 8 + 2 * qi;
        float bx = bias[col], by = bias[col + 1];
        #pragma unroll
        for (int mt = 0; mt < 2; mt++) {
            int r0 = row0 + wm * 32 + mt * 16 + qp;
            float v0 = acc[mt][nt][0] + bx;
            float v1 = acc[mt][nt][1] + by;
            float v2 = acc[mt][nt][2] + bx;
            float v3 = acc[mt][nt][3] + by;
            if (do_relu) {
                v0 = fmaxf(v0, 0.f); v1 = fmaxf(v1, 0.f);
                v2 = fmaxf(v2, 0.f); v3 = fmaxf(v3, 0.f);
            }
            *(float2*)(C + (size_t)r0 * (2 * OUTD) + coloff + col)       = make_float2(v0, v1);
            *(float2*)(C + (size_t)(r0 + 8) * (2 * OUTD) + coloff + col) = make_float2(v2, v3);
        }
    }
}

// ---------------- host launcher ----------------
extern "C" void kernel_launch(void* const* d_in, const int* in_sizes, int n_in,
                              void* d_out, int out_size) {
    const int*   ids   = (const int*)d_in[0];
    const int*   adj   = (const int*)d_in[1];
    const float* feats = (const float*)d_in[2];
    const float* W1x   = (const float*)d_in[3];
    const float* b1x   = (const float*)d_in[4];
    const float* W1n   = (const float*)d_in[5];
    const float* b1n   = (const float*)d_in[6];
    const float* W2x   = (const float*)d_in[7];
    const float* b2x   = (const float*)d_in[8];
    const float* W2n   = (const float*)d_in[9];
    const float* b2n   = (const float*)d_in[10];
    float* out = (float*)d_out;

    float *p_m2, *p_z1, *p_m1, *p_z0, *p_m3;
    int *p_ids1, *p_ids2;
    cudaGetSymbolAddress((void**)&p_m2,  d_m2);
    cudaGetSymbolAddress((void**)&p_z1,  d_z1);
    cudaGetSymbolAddress((void**)&p_m1,  d_m1);
    cudaGetSymbolAddress((void**)&p_z0,  d_z0);
    cudaGetSymbolAddress((void**)&p_m3,  d_m3);
    cudaGetSymbolAddress((void**)&p_ids1, d_ids1);
    cudaGetSymbolAddress((void**)&p_ids2, d_ids2);

    const int GEMM_SMEM = GEMM_SMEM_WORDS * 4;   // 55296 bytes
    cudaFuncSetAttribute(gemm_tc_kernel,
                         cudaFuncAttributeMaxDynamicSharedMemorySize, GEMM_SMEM);

    // 1. permutations (threefry, partitionable, bits1 ^ bits2)
    setup_perm_kernel<<<1, 128>>>();
    // 2. weight fp16 hi/lo split
    split_w_kernel<<<dim3(WSZH / 256, 4), 256>>>(W1x, W1n, W2x, W2n);
    // 3. neighbor id tables
    build_ids_kernel<<<(M1 + 255) / 256, 256>>>(ids, adj);
    // 4. m2 = mean_{fan2}(feats[ids2])   [25600,256]
    mean4_kernel<FAN2><<<M1 / 4, 256>>>(feats, p_ids2, p_m2);
    // 5. z1 = relu([feats[ids1]@W1x^T + b1x | m2@W1n^T + b1n])   (one launch, y=2)
    gemm_tc_kernel<<<dim3(M1 / GBM, 2), 256, GEMM_SMEM>>>(
        feats, p_ids1, p_m2, nullptr, 0, 1, b1x, b1n, p_z1, 1);
    // 6. m1 = mean_{fan1}(feats[ids1])   [1024,256]
    mean4_kernel<FAN1><<<BATCH / 4, 256>>>(feats, p_ids1, p_m1);
    // 7. z0 = relu([feats[ids]@W1x^T + b1x | m1@W1n^T + b1n])
    gemm_tc_kernel<<<dim3(BATCH / GBM, 2), 256, GEMM_SMEM>>>(
        feats, ids, p_m1, nullptr, 0, 1, b1x, b1n, p_z0, 1);
    // 8. m3 = mean_{fan1}(z1)   [1024,256]
    mean4_kernel<FAN1><<<BATCH / 4, 256>>>(p_z1, nullptr, p_m3);
    // 9. out = [z0@W2x^T + b2x | m3@W2n^T + b2n]   (no relu)
    gemm_tc_kernel<<<dim3(BATCH / GBM, 2), 256, GEMM_SMEM>>>(
        p_z0, nullptr, p_m3, nullptr, 2, 3, b2x, b2n, out, 0);
}

// round 7
// speedup vs baseline: 2.3147x; 1.0302x over previous
#include <cuda_runtime.h>
#include <cuda_fp16.h>
#include <cstdint>
#include <cstddef>

// ---------------- problem constants ----------------
#define NNODES   100000
#define DFEAT    256
#define MAXDEG   128
#define BATCH    1024
#define FAN1     25
#define FAN2     10
#define OUTD     128           // per-branch output
#define M1       (BATCH*FAN1)          // 25600
#define M2       (BATCH*FAN1*FAN2)     // 256000
#define WSZH     (OUTD * DFEAT / 2)    // half2 words per weight matrix = 16384

// ---------------- scratch (device globals; no allocation APIs) ----------------
__device__ int      d_cols1[FAN1];
__device__ int      d_cols2[FAN2];
__device__ int      d_ids1[M1];
__device__ int      d_ids2[M2];
__device__ float    d_z1[M1 * DFEAT];     // layer-1 output for ids1 rows
__device__ float    d_m1[BATCH * DFEAT];  // mean over fan1 of feats[ids1]
__device__ float    d_z0[BATCH * DFEAT];  // layer-1 output for ids rows
__device__ float    d_m3[BATCH * DFEAT];  // mean over fan1 of z1
__device__ uint32_t d_Whh[4 * WSZH];      // fp16 hi of weights, [n][k] half2-packed
__device__ uint32_t d_Wll[4 * WSZH];      // fp16 lo

// ---------------- threefry2x32 (JAX-exact, 20 rounds) ----------------
__device__ __forceinline__ uint32_t rotl32(uint32_t v, int r) {
    return (v << r) | (v >> (32 - r));
}

__device__ __forceinline__ void tf2x32(uint32_t k0, uint32_t k1,
                                       uint32_t x0, uint32_t x1,
                                       uint32_t& y0, uint32_t& y1) {
    uint32_t ks0 = k0, ks1 = k1, ks2 = k0 ^ k1 ^ 0x1BD11BDAu;
    x0 += ks0; x1 += ks1;
    const int r0[4] = {13, 15, 26, 6};
    const int r1[4] = {17, 29, 16, 24};
#define TF_G(RR) { x0 += x1; x1 = rotl32(x1, RR[0]); x1 ^= x0; \
                   x0 += x1; x1 = rotl32(x1, RR[1]); x1 ^= x0; \
                   x0 += x1; x1 = rotl32(x1, RR[2]); x1 ^= x0; \
                   x0 += x1; x1 = rotl32(x1, RR[3]); x1 ^= x0; }
    TF_G(r0); x0 += ks1; x1 += ks2 + 1u;
    TF_G(r1); x0 += ks2; x1 += ks0 + 2u;
    TF_G(r0); x0 += ks0; x1 += ks1 + 3u;
    TF_G(r1); x0 += ks1; x1 += ks2 + 4u;
    TF_G(r0); x0 += ks2; x1 += ks0 + 5u;
#undef TF_G
    y0 = x0; y1 = x1;
}

// jax.random.permutation(k, 128) for k1,k2 = split(key(42)),
// partitionable semantics; random_bits(32) = bits1 ^ bits2 (VERIFIED round 4)
__global__ void setup_perm_kernel() {
    int t = threadIdx.x;  // 128 threads
    uint32_t k1a, k1b, k2a, k2b;
    tf2x32(0u, 42u, 0u, 0u, k1a, k1b);
    tf2x32(0u, 42u, 0u, 1u, k2a, k2b);
    uint32_t s1a, s1b, s2a, s2b;
    tf2x32(k1a, k1b, 0u, 1u, s1a, s1b);
    tf2x32(k2a, k2b, 0u, 1u, s2a, s2b);

    __shared__ uint32_t keys[MAXDEG];
    uint32_t b1, b2;

    tf2x32(s1a, s1b, 0u, (uint32_t)t, b1, b2);
    keys[t] = b1 ^ b2;
    __syncthreads();
    {
        uint32_t me = keys[t];
        int rank = 0;
        #pragma unroll 8
        for (int j = 0; j < MAXDEG; j++) {
            uint32_t kj = keys[j];
            rank += (kj < me) || (kj == me && j < t);
        }
        if (rank < FAN1) d_cols1[rank] = t;
    }
    __syncthreads();

    tf2x32(s2a, s2b, 0u, (uint32_t)t, b1, b2);
    keys[t] = b1 ^ b2;
    __syncthreads();
    {
        uint32_t me = keys[t];
        int rank = 0;
        #pragma unroll 8
        for (int j = 0; j < MAXDEG; j++) {
            uint32_t kj = keys[j];
            rank += (kj < me) || (kj == me && j < t);
        }
        if (rank < FAN2) d_cols2[rank] = t;
    }
}

// Build ids1[B*25] and ids2[B*250]
__global__ void build_ids_kernel(const int* __restrict__ ids,
                                 const int* __restrict__ adj) {
    int i = blockIdx.x * blockDim.x + threadIdx.x;
    if (i >= M1) return;
    int b = i / FAN1, s = i - b * FAN1;
    int id0 = ids[b];
    int id1 = adj[(size_t)id0 * MAXDEG + d_cols1[s]];
    d_ids1[i] = id1;
    const int* arow = adj + (size_t)id1 * MAXDEG;
    #pragma unroll
    for (int j = 0; j < FAN2; j++) {
        d_ids2[(size_t)i * FAN2 + j] = arow[d_cols2[j]];
    }
}

// mean over NS rows, 4 output rows per block, float4 lanes (256 threads)
template <int NS>
__global__ void mean4_kernel(const float* __restrict__ src,
                             const int* __restrict__ idx,
                             float* __restrict__ out) {
    __shared__ int sidx[4][NS];
    int t = threadIdx.x;
    int row0 = blockIdx.x * 4;
    if (t < 4 * NS) {
        int rr = t / NS, jj = t - rr * NS;
        sidx[rr][jj] = idx ? idx[(size_t)(row0 + rr) * NS + jj]
                           : (row0 + rr) * NS + jj;
    }
    __syncthreads();
    int rr = t >> 6;
    int c4 = (t & 63) * 4;
    float4 s = make_float4(0.f, 0.f, 0.f, 0.f);
    #pragma unroll
    for (int j = 0; j < NS; j++) {
        const float4 v = *(const float4*)(src + (size_t)sidx[rr][j] * DFEAT + c4);
        s.x += v.x; s.y += v.y; s.z += v.z; s.w += v.w;
    }
    const float inv = 1.0f / NS;
    s.x *= inv; s.y *= inv; s.z *= inv; s.w *= inv;
    *(float4*)(out + (size_t)(row0 + rr) * DFEAT + c4) = s;
}

// one-shot fp16 hi/lo split of the 4 weight matrices, [n][k] half2-packed
__global__ void split_w_kernel(const float* __restrict__ W1x,
                               const float* __restrict__ W1n,
                               const float* __restrict__ W2x,
                               const float* __restrict__ W2n) {
    int m = blockIdx.y;
    const float* W = (m == 0) ? W1x : (m == 1) ? W1n : (m == 2) ? W2x : W2n;
    int i = blockIdx.x * blockDim.x + threadIdx.x;   // half2-pair index
    if (i < WSZH) {
        float w0 = W[2 * i], w1 = W[2 * i + 1];
        __half h0 = __float2half_rn(w0), h1 = __float2half_rn(w1);
        float l0 = w0 - __half2float(h0);
        float l1 = w1 - __half2float(h1);
        __half2 hh = __halves2half2(h0, h1);
        __half2 ll = __floats2half2_rn(l0, l1);
        d_Whh[(size_t)m * WSZH + i] = *(uint32_t*)&hh;
        d_Wll[(size_t)m * WSZH + i] = *(uint32_t*)&ll;
    }
}

#define MMA_F16(d, a0, a1, a2, a3, b0, b1) \
    asm volatile( \
        "mma.sync.aligned.m16n8k16.row.col.f32.f16.f16.f32 " \
        "{%0,%1,%2,%3}, {%4,%5,%6,%7}, {%8,%9}, {%0,%1,%2,%3};" \
        : "+f"((d)[0]), "+f"((d)[1]), "+f"((d)[2]), "+f"((d)[3]) \
        : "r"(a0), "r"(a1), "r"(a2), "r"(a3), "r"(b0), "r"(b1))

// ---------------- tensor-core fused gather(-mean)-GEMM (fp16 3-way split) -------
// gridDim.y = 2 selects branch. Branch 1 may fuse an NM-row gather-mean into the
// A load (NM template param; NM=1 -> plain gather / contiguous).
// C[row, b*128 + c] = act( sum_k A_b[row,k] * W_b[c,k] + bias_b[c] )
// Block: 256 thr (8 warps, 2x4), BM=64, BN=128, K=256 in 4 chunks of 64.
// smem half2-words, row stride 36 (== 4 mod 32: conflict-free fragments).
#define GBM   64
#define KCH   64
#define STR   36
#define SM_AH 0
#define SM_AL (GBM * STR)
#define SM_BH (2 * GBM * STR)
#define SM_BL (2 * GBM * STR + OUTD * STR)
#define GEMM_SMEM_WORDS (2 * GBM * STR + 2 * OUTD * STR)   // 13824 words = 55296 B

template <int NM>
__global__ __launch_bounds__(256, 3)
void gemm_tc_kernel(const float* __restrict__ A0, const int* __restrict__ g0,
                    const float* __restrict__ A1, const int* __restrict__ g1,
                    int wsel0, int wsel1,
                    const float* __restrict__ bias0, const float* __restrict__ bias1,
                    float* __restrict__ C, int do_relu) {
    extern __shared__ uint32_t smx[];
    uint32_t* Ash = smx + SM_AH;
    uint32_t* Asl = smx + SM_AL;
    uint32_t* Bsh = smx + SM_BH;
    uint32_t* Bsl = smx + SM_BL;
    __shared__ int rowidx[GBM];

    int branch = blockIdx.y;
    const float* Asrc = branch ? A1 : A0;
    const int*   gidx = branch ? g1 : g0;
    const uint32_t* Wh = d_Whh + (size_t)(branch ? wsel1 : wsel0) * WSZH;
    const uint32_t* Wl = d_Wll + (size_t)(branch ? wsel1 : wsel0) * WSZH;
    const float* bias = branch ? bias1 : bias0;
    int coloff = branch * OUTD;
    bool meanpath = (branch == 1) && (NM > 1);

    int t = threadIdx.x;
    int row0 = blockIdx.x * GBM;
    if (!meanpath && t < GBM) rowidx[t] = gidx ? gidx[row0 + t] : (row0 + t);
    __syncthreads();

    int wid = t >> 5, lane = t & 31;
    int wm = wid & 1;        // 0..1 -> 32-row slab
    int wn = wid >> 1;       // 0..3 -> 32-col slab
    int qp = lane >> 2;      // 0..7
    int qi = lane & 3;       // 0..3

    float acc[2][4][4];
    #pragma unroll
    for (int mt = 0; mt < 2; mt++)
        #pragma unroll
        for (int nt = 0; nt < 4; nt++)
            #pragma unroll
            for (int j = 0; j < 4; j++) acc[mt][nt][j] = 0.f;

    for (int kc = 0; kc < 4; kc++) {
        // ---- A chunk: 64 rows x 64 k = 1024 float4 / 256 thr = 4 each
        #pragma unroll
        for (int i = 0; i < 4; i++) {
            int idx = t + i * 256;
            int r  = idx >> 4;
            int k4 = idx & 15;
            float4 v;
            if (!meanpath) {
                v = *(const float4*)(Asrc + (size_t)rowidx[r] * DFEAT
                                     + kc * KCH + k4 * 4);
            } else {
                // fused NM-row gather-mean (fp32 accumulate)
                const int* gr = gidx ? (gidx + (size_t)(row0 + r) * NM) : nullptr;
                float4 s = make_float4(0.f, 0.f, 0.f, 0.f);
                #pragma unroll
                for (int j = 0; j < NM; j++) {
                    int src = gr ? __ldg(gr + j) : ((row0 + r) * NM + j);
                    const float4 u = *(const float4*)(Asrc + (size_t)src * DFEAT
                                                      + kc * KCH + k4 * 4);
                    s.x += u.x; s.y += u.y; s.z += u.z; s.w += u.w;
                }
                const float inv = 1.0f / NM;
                v = make_float4(s.x * inv, s.y * inv, s.z * inv, s.w * inv);
            }
            __half2 h01 = __floats2half2_rn(v.x, v.y);
            __half2 h23 = __floats2half2_rn(v.z, v.w);
            float2 f01 = __half22float2(h01);
            float2 f23 = __half22float2(h23);
            __half2 l01 = __floats2half2_rn(v.x - f01.x, v.y - f01.y);
            __half2 l23 = __floats2half2_rn(v.z - f23.x, v.w - f23.y);
            uint2 hw, lw;
            hw.x = *(uint32_t*)&h01; hw.y = *(uint32_t*)&h23;
            lw.x = *(uint32_t*)&l01; lw.y = *(uint32_t*)&l23;
            *(uint2*)(Ash + r * STR + k4 * 2) = hw;
            *(uint2*)(Asl + r * STR + k4 * 2) = lw;
        }
        // ---- B chunk (pre-split): 128 rows x 32 half2-words -> 4 uint4 each
        #pragma unroll
        for (int i = 0; i < 4; i++) {
            int idx = t + i * 256;
            int r  = idx >> 3;
            int w4 = idx & 7;
            *(uint4*)(Bsh + r * STR + w4 * 4) =
                *(const uint4*)(Wh + (size_t)r * (DFEAT / 2) + kc * (KCH / 2) + w4 * 4);
            *(uint4*)(Bsl + r * STR + w4 * 4) =
                *(const uint4*)(Wl + (size_t)r * (DFEAT / 2) + kc * (KCH / 2) + w4 * 4);
        }
        __syncthreads();

        #pragma unroll
        for (int kk2 = 0; kk2 < KCH / 2; kk2 += 8) {   // one m16n8k16 per step
            uint32_t ah[2][4], al[2][4];
            #pragma unroll
            for (int mt = 0; mt < 2; mt++) {
                int rm = wm * 32 + mt * 16 + qp;
                ah[mt][0] = Ash[rm * STR + kk2 + qi];
                ah[mt][1] = Ash[(rm + 8) * STR + kk2 + qi];
                ah[mt][2] = Ash[rm * STR + kk2 + qi + 4];
                ah[mt][3] = Ash[(rm + 8) * STR + kk2 + qi + 4];
                al[mt][0] = Asl[rm * STR + kk2 + qi];
                al[mt][1] = Asl[(rm + 8) * STR + kk2 + qi];
                al[mt][2] = Asl[rm * STR + kk2 + qi + 4];
                al[mt][3] = Asl[(rm + 8) * STR + kk2 + qi + 4];
            }
            #pragma unroll
            for (int nt = 0; nt < 4; nt++) {
                int nb = wn * 32 + nt * 8 + qp;
                uint32_t bh0 = Bsh[nb * STR + kk2 + qi];
                uint32_t bh1 = Bsh[nb * STR + kk2 + qi + 4];
                uint32_t bl0 = Bsl[nb * STR + kk2 + qi];
                uint32_t bl1 = Bsl[nb * STR + kk2 + qi + 4];
                #pragma unroll
                for (int mt = 0; mt < 2; mt++) {
                    MMA_F16(acc[mt][nt], ah[mt][0], ah[mt][1], ah[mt][2], ah[mt][3], bh0, bh1);
                    MMA_F16(acc[mt][nt], ah[mt][0], ah[mt][1], ah[mt][2], ah[mt][3], bl0, bl1);
                    MMA_F16(acc[mt][nt], al[mt][0], al[mt][1], al[mt][2], al[mt][3], bh0, bh1);
                }
            }
        }
        __syncthreads();
    }

    // ---- epilogue: bias + optional relu, write to C (row stride 2*OUTD)
    #pragma unroll
    for (int nt = 0; nt < 4; nt++) {
        int col = wn * 32 + nt * 8 + 2 * qi;
        float bx = bias[col], by = bias[col + 1];
        #pragma unroll
        for (int mt = 0; mt < 2; mt++) {
            int r0 = row0 + wm * 32 + mt * 16 + qp;
            float v0 = acc[mt][nt][0] + bx;
            float v1 = acc[mt][nt][1] + by;
            float v2 = acc[mt][nt][2] + bx;
            float v3 = acc[mt][nt][3] + by;
            if (do_relu) {
                v0 = fmaxf(v0, 0.f); v1 = fmaxf(v1, 0.f);
                v2 = fmaxf(v2, 0.f); v3 = fmaxf(v3, 0.f);
            }
            *(float2*)(C + (size_t)r0 * (2 * OUTD) + coloff + col)       = make_float2(v0, v1);
            *(float2*)(C + (size_t)(r0 + 8) * (2 * OUTD) + coloff + col) = make_float2(v2, v3);
        }
    }
}

// ---------------- host launcher ----------------
extern "C" void kernel_launch(void* const* d_in, const int* in_sizes, int n_in,
                              void* d_out, int out_size) {
    const int*   ids   = (const int*)d_in[0];
    const int*   adj   = (const int*)d_in[1];
    const float* feats = (const float*)d_in[2];
    const float* W1x   = (const float*)d_in[3];
    const float* b1x   = (const float*)d_in[4];
    const float* W1n   = (const float*)d_in[5];
    const float* b1n   = (const float*)d_in[6];
    const float* W2x   = (const float*)d_in[7];
    const float* b2x   = (const float*)d_in[8];
    const float* W2n   = (const float*)d_in[9];
    const float* b2n   = (const float*)d_in[10];
    float* out = (float*)d_out;

    float *p_z1, *p_m1, *p_z0, *p_m3;
    int *p_ids1, *p_ids2;
    cudaGetSymbolAddress((void**)&p_z1,  d_z1);
    cudaGetSymbolAddress((void**)&p_m1,  d_m1);
    cudaGetSymbolAddress((void**)&p_z0,  d_z0);
    cudaGetSymbolAddress((void**)&p_m3,  d_m3);
    cudaGetSymbolAddress((void**)&p_ids1, d_ids1);
    cudaGetSymbolAddress((void**)&p_ids2, d_ids2);

    const int GEMM_SMEM = GEMM_SMEM_WORDS * 4;   // 55296 bytes
    cudaFuncSetAttribute(gemm_tc_kernel<10>,
                         cudaFuncAttributeMaxDynamicSharedMemorySize, GEMM_SMEM);
    cudaFuncSetAttribute(gemm_tc_kernel<1>,
                         cudaFuncAttributeMaxDynamicSharedMemorySize, GEMM_SMEM);

    // 1. permutations (threefry, partitionable, bits1 ^ bits2)
    setup_perm_kernel<<<1, 128>>>();
    // 2. weight fp16 hi/lo split
    split_w_kernel<<<dim3(WSZH / 256, 4), 256>>>(W1x, W1n, W2x, W2n);
    // 3. neighbor id tables
    build_ids_kernel<<<(M1 + 255) / 256, 256>>>(ids, adj);
    // 4. m1 = mean_{fan1}(feats[ids1])   [1024,256]
    mean4_kernel<FAN1><<<BATCH / 4, 256>>>(feats, p_ids1, p_m1);
    // 5. z1 = relu([feats[ids1]@W1x^T | mean10(feats[ids2])@W1n^T] + b)
    //    fan-10 mean FUSED into branch-1 A-load
    gemm_tc_kernel<10><<<dim3(M1 / GBM, 2), 256, GEMM_SMEM>>>(
        feats, p_ids1, feats, p_ids2, 0, 1, b1x, b1n, p_z1, 1);
    // 6. z0 = relu([feats[ids]@W1x^T | m1@W1n^T] + b)
    gemm_tc_kernel<1><<<dim3(BATCH / GBM, 2), 256, GEMM_SMEM>>>(
        feats, ids, p_m1, nullptr, 0, 1, b1x, b1n, p_z0, 1);
    // 7. m3 = mean_{fan1}(z1)   [1024,256]
    mean4_kernel<FAN1><<<BATCH / 4, 256>>>(p_z1, nullptr, p_m3);
    // 8. out = [z0@W2x^T + b2x | m3@W2n^T + b2n]   (no relu)
    gemm_tc_kernel<1><<<dim3(BATCH / GBM, 2), 256, GEMM_SMEM>>>(
        p_z0, nullptr, p_m3, nullptr, 2, 3, b2x, b2n, out, 0);
}